// round 1
// baseline (speedup 1.0000x reference)
#include <cuda_runtime.h>

// ---------------------------------------------------------------------------
// Attention: out = softmax((x@Wq^T+bq)(x@Wk^T+bk)^T / scale) @ (x@Wv^T+bv)
// B=4, N=4096, D=256, fp32.
// Pipeline: [QKV sgemm x3] -> [S = Q@K^T sgemm, batched] -> [row softmax] ->
//           [out = P@V sgemm, batched]
// ---------------------------------------------------------------------------

#define ATT_B 4
#define ATT_N 4096
#define ATT_D 256
#define ATT_M (ATT_B * ATT_N)   // 16384

// Scratch in device globals (no allocations allowed in kernel_launch).
__device__ float g_Q[ATT_M * ATT_D];
__device__ float g_K[ATT_M * ATT_D];
__device__ float g_V[ATT_M * ATT_D];
__device__ float g_S[(size_t)ATT_B * ATT_N * ATT_N];  // 268 MB, reused for P

// ---------------------------------------------------------------------------
// Tiled SGEMM: C[M,N] = A[M,K] * op(B) (+ bias[n])
//   B_NT = true : B stored [N,K] row-major (C = A @ B^T)   -- QKV proj, Q@K^T
//   B_NT = false: B stored [K,N] row-major (C = A @ B)     -- P@V
// BM=BN=128, BK=16, 256 threads, 8x8 per thread.
// All dims here are multiples of the tile sizes -> no bounds checks.
// ---------------------------------------------------------------------------
#define BM 128
#define BN 128
#define BK 16
#define TM 8
#define TN 8
#define PAD 4

template <bool B_NT, bool BIAS>
__global__ __launch_bounds__(256)
void sgemm_kernel(const float* __restrict__ A,
                  const float* __restrict__ Bm,
                  const float* __restrict__ bias,
                  float* __restrict__ C,
                  int M, int N, int K,
                  long strideA, long strideB, long strideC)
{
    __shared__ float As[BK][BM + PAD];
    __shared__ float Bs[BK][BN + PAD];

    const int bz = blockIdx.z;
    A  += (long)bz * strideA;
    Bm += (long)bz * strideB;
    C  += (long)bz * strideC;

    const int cRow = blockIdx.y;   // M-tile index
    const int cCol = blockIdx.x;   // N-tile index
    const int tid  = threadIdx.x;
    const int tx   = tid % 16;     // n micro-tile
    const int ty   = tid / 16;     // m micro-tile

    const float* Aptr = A + (long)cRow * BM * K;
    const float* Bptr = B_NT ? (Bm + (long)cCol * BN * K)
                             : (Bm + cCol * BN);

    // load mapping (float4 per thread per pass)
    const int aRow = tid / 4;            // 0..63  (m or n row)
    const int aCol = (tid % 4) * 4;      // k offset
    const int bRowNN = tid / 32;         // 0..7   (k row, NN path)
    const int bColNN = (tid % 32) * 4;   // n offset, NN path

    float acc[TM][TN] = {};

    for (int k0 = 0; k0 < K; k0 += BK) {
        // --- load A tile, transposed to As[k][m] ---
        #pragma unroll
        for (int r = 0; r < 2; r++) {
            int m = aRow + r * 64;
            float4 v = *(const float4*)(Aptr + (long)m * K + k0 + aCol);
            As[aCol + 0][m] = v.x;
            As[aCol + 1][m] = v.y;
            As[aCol + 2][m] = v.z;
            As[aCol + 3][m] = v.w;
        }
        // --- load B tile to Bs[k][n] ---
        if (B_NT) {
            #pragma unroll
            for (int r = 0; r < 2; r++) {
                int n = aRow + r * 64;
                float4 v = *(const float4*)(Bptr + (long)n * K + k0 + aCol);
                Bs[aCol + 0][n] = v.x;
                Bs[aCol + 1][n] = v.y;
                Bs[aCol + 2][n] = v.z;
                Bs[aCol + 3][n] = v.w;
            }
        } else {
            #pragma unroll
            for (int r = 0; r < 2; r++) {
                int kk = bRowNN + r * 8;
                float4 v = *(const float4*)(Bptr + (long)(k0 + kk) * N + bColNN);
                *(float4*)&Bs[kk][bColNN] = v;
            }
        }
        __syncthreads();

        // --- compute ---
        #pragma unroll
        for (int k = 0; k < BK; k++) {
            float ra[TM], rb[TN];
            const float4* a4 = (const float4*)&As[k][ty * TM];
            const float4* b4 = (const float4*)&Bs[k][tx * TN];
            float4 a0 = a4[0], a1 = a4[1];
            float4 b0 = b4[0], b1 = b4[1];
            ra[0]=a0.x; ra[1]=a0.y; ra[2]=a0.z; ra[3]=a0.w;
            ra[4]=a1.x; ra[5]=a1.y; ra[6]=a1.z; ra[7]=a1.w;
            rb[0]=b0.x; rb[1]=b0.y; rb[2]=b0.z; rb[3]=b0.w;
            rb[4]=b1.x; rb[5]=b1.y; rb[6]=b1.z; rb[7]=b1.w;
            #pragma unroll
            for (int i = 0; i < TM; i++)
                #pragma unroll
                for (int j = 0; j < TN; j++)
                    acc[i][j] += ra[i] * rb[j];
        }
        __syncthreads();
    }

    // --- epilogue ---
    #pragma unroll
    for (int i = 0; i < TM; i++) {
        long m = (long)cRow * BM + ty * TM + i;
        #pragma unroll
        for (int j = 0; j < TN; j += 4) {
            int n = cCol * BN + tx * TN + j;
            float4 v;
            v.x = acc[i][j + 0];
            v.y = acc[i][j + 1];
            v.z = acc[i][j + 2];
            v.w = acc[i][j + 3];
            if (BIAS) {
                v.x += bias[n + 0];
                v.y += bias[n + 1];
                v.z += bias[n + 2];
                v.w += bias[n + 3];
            }
            *(float4*)(C + m * N + n) = v;
        }
    }
}

// ---------------------------------------------------------------------------
// Row softmax over S (in place), with 1/scale applied first.
// One block per row of 4096; row held in registers (16 floats/thread).
// ---------------------------------------------------------------------------
__global__ __launch_bounds__(256)
void softmax_kernel(float* __restrict__ S, const float* __restrict__ scale_ptr)
{
    const long row = blockIdx.x;
    float* p = S + row * ATT_N;
    const float inv_scale = 1.0f / scale_ptr[0];
    const int t = threadIdx.x;

    float x[16];
    float mx = -1e30f;
    #pragma unroll
    for (int i = 0; i < 16; i++) {
        x[i] = p[t + i * 256] * inv_scale;
        mx = fmaxf(mx, x[i]);
    }

    __shared__ float red[256];
    red[t] = mx;
    __syncthreads();
    #pragma unroll
    for (int s = 128; s > 0; s >>= 1) {
        if (t < s) red[t] = fmaxf(red[t], red[t + s]);
        __syncthreads();
    }
    mx = red[0];
    __syncthreads();

    float sum = 0.0f;
    #pragma unroll
    for (int i = 0; i < 16; i++) {
        x[i] = __expf(x[i] - mx);
        sum += x[i];
    }
    red[t] = sum;
    __syncthreads();
    #pragma unroll
    for (int s = 128; s > 0; s >>= 1) {
        if (t < s) red[t] += red[t + s];
        __syncthreads();
    }
    const float rinv = 1.0f / red[0];
    #pragma unroll
    for (int i = 0; i < 16; i++)
        p[t + i * 256] = x[i] * rinv;
}

// ---------------------------------------------------------------------------
// Launch
// ---------------------------------------------------------------------------
extern "C" void kernel_launch(void* const* d_in, const int* in_sizes, int n_in,
                              void* d_out, int out_size)
{
    const float* x     = (const float*)d_in[0];
    const float* Wq    = (const float*)d_in[1];
    const float* bq    = (const float*)d_in[2];
    const float* Wk    = (const float*)d_in[3];
    const float* bk    = (const float*)d_in[4];
    const float* Wv    = (const float*)d_in[5];
    const float* bv    = (const float*)d_in[6];
    const float* scale = (const float*)d_in[7];
    float* out = (float*)d_out;

    float* Q;  cudaGetSymbolAddress((void**)&Q, g_Q);
    float* Kp; cudaGetSymbolAddress((void**)&Kp, g_K);
    float* V;  cudaGetSymbolAddress((void**)&V, g_V);
    float* S;  cudaGetSymbolAddress((void**)&S, g_S);

    // 1) QKV projections: [16384,256] = x[16384,256] @ W^T[256,256] + b
    {
        dim3 grid(ATT_D / BN, ATT_M / BM, 1);
        sgemm_kernel<true, true><<<grid, 256>>>(x, Wq, bq, Q,  ATT_M, ATT_D, ATT_D, 0, 0, 0);
        sgemm_kernel<true, true><<<grid, 256>>>(x, Wk, bk, Kp, ATT_M, ATT_D, ATT_D, 0, 0, 0);
        sgemm_kernel<true, true><<<grid, 256>>>(x, Wv, bv, V,  ATT_M, ATT_D, ATT_D, 0, 0, 0);
    }

    // 2) S[b] = Q[b] @ K[b]^T   (4096 x 4096, K=256), batched over z
    {
        dim3 grid(ATT_N / BN, ATT_N / BM, ATT_B);
        sgemm_kernel<true, false><<<grid, 256>>>(
            Q, Kp, nullptr, S, ATT_N, ATT_N, ATT_D,
            (long)ATT_N * ATT_D, (long)ATT_N * ATT_D, (long)ATT_N * ATT_N);
    }

    // 3) P = softmax(S / scale) rows, in place
    softmax_kernel<<<ATT_B * ATT_N, 256>>>(S, scale);

    // 4) out[b] = P[b] @ V[b]   (4096 x 256, K=4096), batched over z
    {
        dim3 grid(ATT_D / BN, ATT_N / BM, ATT_B);
        sgemm_kernel<false, false><<<grid, 256>>>(
            S, V, nullptr, out, ATT_N, ATT_D, ATT_N,
            (long)ATT_N * ATT_N, (long)ATT_N * ATT_D, (long)ATT_N * ATT_D);
    }
}

// round 6
// speedup vs baseline: 1.6817x; 1.6817x over previous
#include <cuda_runtime.h>
#include <cuda_bf16.h>
#include <cstdint>

#define ATT_B 4
#define ATT_N 4096
#define ATT_D 256
#define ATT_M (ATT_B * ATT_N)   // 16384

// ---------------- scratch (no allocations allowed) ----------------
__device__ float g_Q[ATT_M * ATT_D];
__device__ float g_K[ATT_M * ATT_D];
__device__ float g_V[ATT_M * ATT_D];
__device__ float g_S[(size_t)ATT_B * ATT_N * ATT_N];            // scores fp32
__device__ __nv_bfloat16 g_Qh[ATT_M * ATT_D], g_Ql[ATT_M * ATT_D];
__device__ __nv_bfloat16 g_Kh[ATT_M * ATT_D], g_Kl[ATT_M * ATT_D];
__device__ __nv_bfloat16 g_VTh[ATT_M * ATT_D], g_VTl[ATT_M * ATT_D];   // [B][D][N]
__device__ __nv_bfloat16 g_Ph[(size_t)ATT_B * ATT_N * ATT_N];
__device__ __nv_bfloat16 g_Pl[(size_t)ATT_B * ATT_N * ATT_N];

// ---------------- helpers ----------------
__device__ __forceinline__ uint32_t smem_u32(const void* p) {
    uint32_t a;
    asm("{ .reg .u64 t; cvta.to.shared.u64 t, %1; cvt.u32.u64 %0, t; }"
        : "=r"(a) : "l"(p));
    return a;
}
__device__ __forceinline__ void ldsm4(uint32_t* r, uint32_t addr) {
    asm volatile("ldmatrix.sync.aligned.m8n8.x4.shared.b16 {%0,%1,%2,%3}, [%4];"
                 : "=r"(r[0]), "=r"(r[1]), "=r"(r[2]), "=r"(r[3]) : "r"(addr));
}
__device__ __forceinline__ void mma16816(float* c, const uint32_t* a,
                                         uint32_t b0, uint32_t b1) {
    asm volatile(
        "mma.sync.aligned.m16n8k16.row.col.f32.bf16.bf16.f32 "
        "{%0,%1,%2,%3}, {%4,%5,%6,%7}, {%8,%9}, {%0,%1,%2,%3};"
        : "+f"(c[0]), "+f"(c[1]), "+f"(c[2]), "+f"(c[3])
        : "r"(a[0]), "r"(a[1]), "r"(a[2]), "r"(a[3]), "r"(b0), "r"(b1));
}
__device__ __forceinline__ void cp_async16(uint32_t saddr, const void* gaddr) {
    asm volatile("cp.async.ca.shared.global [%0], [%1], 16;"
                 :: "r"(saddr), "l"(gaddr) : "memory");
}
__device__ __forceinline__ void cp_commit() {
    asm volatile("cp.async.commit_group;" ::: "memory");
}
template <int N>
__device__ __forceinline__ void cp_wait() {
    asm volatile("cp.async.wait_group %0;" :: "n"(N) : "memory");
}

// ---------------------------------------------------------------------------
// Warp-MMA GEMM (HMMA via mma.sync): C[M,N] = 3-term bf16 split of
// A[M,K] @ B[N,K]^T, fp32 accumulate.
// BM=BN=128, BK=32, 256 threads (8 warps, 4x2), warp tile 32x64.
// Both tiles stored [row][k] in smem, pitch 40 bf16 (80B, conflict-free LDSM).
// ---------------------------------------------------------------------------
#define MM_PITCH 40
#define MM_TILE  (128 * MM_PITCH)   // bf16 elements per tile buffer

__global__ void __launch_bounds__(256)
mma_gemm(const __nv_bfloat16* __restrict__ Ah, const __nv_bfloat16* __restrict__ Al,
         const __nv_bfloat16* __restrict__ Bh, const __nv_bfloat16* __restrict__ Bl,
         float* __restrict__ C, int K, int ldC,
         long sA, long sB, long sC)
{
    __shared__ __align__(128) __nv_bfloat16 sAt[2][MM_TILE];
    __shared__ __align__(128) __nv_bfloat16 sBt[2][MM_TILE];

    const int tid  = threadIdx.x;
    const int wid  = tid >> 5;
    const int lane = tid & 31;
    const int bz = blockIdx.z;
    const int m0 = blockIdx.y * 128;
    const int n0 = blockIdx.x * 128;
    const int wm = (wid & 3) * 32;   // warp m offset in tile
    const int wn = (wid >> 2) * 64;  // warp n offset in tile

    const __nv_bfloat16* Ah_b = Ah + (long)bz * sA + (long)m0 * K;
    const __nv_bfloat16* Al_b = Al + (long)bz * sA + (long)m0 * K;
    const __nv_bfloat16* Bh_b = Bh + (long)bz * sB + (long)n0 * K;
    const __nv_bfloat16* Bl_b = Bl + (long)bz * sB + (long)n0 * K;

    const int kch = K >> 5;        // 32-wide chunks per phase
    const int nch = 3 * kch;       // phases: (Ah,Bh), (Ah,Bl), (Al,Bh)

    // loader mapping: 512 x 16B per tile, 2 per thread per tile
    const int lrow = tid >> 2;          // 0..63
    const int lq   = tid & 3;           // 16B column within 64B row

    auto issue_chunk = [&](int c) {
        const int phase = c / kch;
        const int kk = (c - phase * kch) << 5;
        const __nv_bfloat16* pa = (phase == 2) ? Al_b : Ah_b;
        const __nv_bfloat16* pb = (phase == 1) ? Bl_b : Bh_b;
        const int buf = c & 1;
        #pragma unroll
        for (int i = 0; i < 2; ++i) {
            const int row = lrow + i * 64;
            const long go = (long)row * K + kk + lq * 8;
            const uint32_t so = row * MM_PITCH + lq * 8;
            cp_async16(smem_u32(&sAt[buf][so]), pa + go);
            cp_async16(smem_u32(&sBt[buf][so]), pb + go);
        }
        cp_commit();
    };

    float acc[2][8][4];
    #pragma unroll
    for (int mi = 0; mi < 2; ++mi)
        #pragma unroll
        for (int ni = 0; ni < 8; ++ni)
            #pragma unroll
            for (int j = 0; j < 4; ++j) acc[mi][ni][j] = 0.0f;

    issue_chunk(0);

    for (int c = 0; c < nch; ++c) {
        if (c + 1 < nch) { issue_chunk(c + 1); cp_wait<1>(); }
        else             { cp_wait<0>(); }
        __syncthreads();

        const int buf = c & 1;
        const uint32_t abase = smem_u32(&sAt[buf][0]);
        const uint32_t bbase = smem_u32(&sBt[buf][0]);
        const int lr = lane & 15;          // ldmatrix row within 16
        const int lc = (lane >> 4) * 16;   // 16B column selector (bytes)

        #pragma unroll
        for (int s = 0; s < 2; ++s) {      // two k16 steps in BK=32
            const uint32_t kb = s * 32 + lc;   // byte offset in row
            uint32_t afr[2][4];
            #pragma unroll
            for (int mi = 0; mi < 2; ++mi)
                ldsm4(afr[mi], abase + (wm + mi * 16 + lr) * (MM_PITCH * 2) + kb);
            uint32_t bfr[4][4];
            #pragma unroll
            for (int nj = 0; nj < 4; ++nj)
                ldsm4(bfr[nj], bbase + (wn + nj * 16 + lr) * (MM_PITCH * 2) + kb);
            #pragma unroll
            for (int mi = 0; mi < 2; ++mi)
                #pragma unroll
                for (int nj = 0; nj < 4; ++nj) {
                    mma16816(acc[mi][nj * 2 + 0], afr[mi], bfr[nj][0], bfr[nj][2]);
                    mma16816(acc[mi][nj * 2 + 1], afr[mi], bfr[nj][1], bfr[nj][3]);
                }
        }
        __syncthreads();
    }

    // epilogue: thread owns rows (lane/4, +8) cols (lane%4)*2 within each m16n8
    float* Cb = C + (long)bz * sC;
    #pragma unroll
    for (int mi = 0; mi < 2; ++mi) {
        const long r0 = m0 + wm + mi * 16 + (lane >> 2);
        #pragma unroll
        for (int ni = 0; ni < 8; ++ni) {
            const int col = n0 + wn + ni * 8 + (lane & 3) * 2;
            float2 v0 = make_float2(acc[mi][ni][0], acc[mi][ni][1]);
            float2 v1 = make_float2(acc[mi][ni][2], acc[mi][ni][3]);
            *(float2*)(Cb + r0 * ldC + col)       = v0;
            *(float2*)(Cb + (r0 + 8) * ldC + col) = v1;
        }
    }
}

// ---------------------------------------------------------------------------
// SIMT SGEMM for QKV projections, fused: z selects (Wq,bq)/(Wk,bk)/(Wv,bv)
// ---------------------------------------------------------------------------
#define BM 128
#define BN 128
#define BK 16
#define PAD 4

__global__ __launch_bounds__(256)
void sgemm_qkv(const float* __restrict__ A,
               const float* __restrict__ W0, const float* __restrict__ b0,
               const float* __restrict__ W1, const float* __restrict__ b1,
               const float* __restrict__ W2, const float* __restrict__ b2,
               float* __restrict__ C0, float* __restrict__ C1, float* __restrict__ C2,
               int K, int N)
{
    const int z = blockIdx.z;
    const float* W    = (z == 0) ? W0 : (z == 1) ? W1 : W2;
    const float* bias = (z == 0) ? b0 : (z == 1) ? b1 : b2;
    float* C          = (z == 0) ? C0 : (z == 1) ? C1 : C2;

    __shared__ float As[BK][BM + PAD];
    __shared__ float Bs[BK][BN + PAD];
    const int cRow = blockIdx.y, cCol = blockIdx.x, tid = threadIdx.x;
    const int tx = tid % 16, ty = tid / 16;
    const float* Aptr = A + (long)cRow * BM * K;
    const float* Bptr = W + (long)cCol * BN * K;
    const int aRow = tid / 4, aCol = (tid % 4) * 4;
    float acc[8][8] = {};

    for (int k0 = 0; k0 < K; k0 += BK) {
        #pragma unroll
        for (int r = 0; r < 2; r++) {
            int m = aRow + r * 64;
            float4 v = *(const float4*)(Aptr + (long)m * K + k0 + aCol);
            As[aCol+0][m]=v.x; As[aCol+1][m]=v.y; As[aCol+2][m]=v.z; As[aCol+3][m]=v.w;
            float4 w = *(const float4*)(Bptr + (long)m * K + k0 + aCol);
            Bs[aCol+0][m]=w.x; Bs[aCol+1][m]=w.y; Bs[aCol+2][m]=w.z; Bs[aCol+3][m]=w.w;
        }
        __syncthreads();
        #pragma unroll
        for (int k = 0; k < BK; k++) {
            float ra[8], rb[8];
            const float4* a4 = (const float4*)&As[k][ty * 8];
            const float4* b4 = (const float4*)&Bs[k][tx * 8];
            float4 a0=a4[0],a1=a4[1],b0v=b4[0],b1v=b4[1];
            ra[0]=a0.x;ra[1]=a0.y;ra[2]=a0.z;ra[3]=a0.w;ra[4]=a1.x;ra[5]=a1.y;ra[6]=a1.z;ra[7]=a1.w;
            rb[0]=b0v.x;rb[1]=b0v.y;rb[2]=b0v.z;rb[3]=b0v.w;rb[4]=b1v.x;rb[5]=b1v.y;rb[6]=b1v.z;rb[7]=b1v.w;
            #pragma unroll
            for (int i = 0; i < 8; i++)
                #pragma unroll
                for (int j = 0; j < 8; j++)
                    acc[i][j] += ra[i] * rb[j];
        }
        __syncthreads();
    }
    #pragma unroll
    for (int i = 0; i < 8; i++) {
        long m = (long)cRow * BM + ty * 8 + i;
        #pragma unroll
        for (int j = 0; j < 8; j += 4) {
            int n = cCol * BN + tx * 8 + j;
            float4 v;
            v.x = acc[i][j+0] + bias[n+0];
            v.y = acc[i][j+1] + bias[n+1];
            v.z = acc[i][j+2] + bias[n+2];
            v.w = acc[i][j+3] + bias[n+3];
            *(float4*)(C + m * N + n) = v;
        }
    }
}

// ---------------------------------------------------------------------------
// elementwise fp32 -> bf16 hi/lo split
// ---------------------------------------------------------------------------
__global__ __launch_bounds__(256)
void split_kernel(const float4* __restrict__ in, __nv_bfloat16* __restrict__ hi,
                  __nv_bfloat16* __restrict__ lo, int n4)
{
    int i = blockIdx.x * 256 + threadIdx.x;
    if (i >= n4) return;
    float4 v = in[i];
    __nv_bfloat16 h0 = __float2bfloat16(v.x), h1 = __float2bfloat16(v.y);
    __nv_bfloat16 h2 = __float2bfloat16(v.z), h3 = __float2bfloat16(v.w);
    __nv_bfloat162 hp0; hp0.x = h0; hp0.y = h1;
    __nv_bfloat162 hp1; hp1.x = h2; hp1.y = h3;
    __nv_bfloat162 lp0;
    lp0.x = __float2bfloat16(v.x - __bfloat162float(h0));
    lp0.y = __float2bfloat16(v.y - __bfloat162float(h1));
    __nv_bfloat162 lp1;
    lp1.x = __float2bfloat16(v.z - __bfloat162float(h2));
    lp1.y = __float2bfloat16(v.w - __bfloat162float(h3));
    ((__nv_bfloat162*)hi)[i * 2 + 0] = hp0;
    ((__nv_bfloat162*)hi)[i * 2 + 1] = hp1;
    ((__nv_bfloat162*)lo)[i * 2 + 0] = lp0;
    ((__nv_bfloat162*)lo)[i * 2 + 1] = lp1;
}

// ---------------------------------------------------------------------------
// V [B*N, D] -> VT [B][D][N] with bf16 hi/lo split (32x32 smem transpose)
// ---------------------------------------------------------------------------
__global__ __launch_bounds__(256)
void vtrans_kernel(const float* __restrict__ V, __nv_bfloat16* __restrict__ VTh,
                   __nv_bfloat16* __restrict__ VTl)
{
    __shared__ float tile[32][33];
    const int b  = blockIdx.z;
    const int d0 = blockIdx.x * 32;
    const int t0 = blockIdx.y * 32;
    const int tx = threadIdx.x & 31;
    const int ty = threadIdx.x >> 5;   // 0..7
    const float* Vb = V + (long)b * ATT_N * ATT_D;
    #pragma unroll
    for (int j = ty; j < 32; j += 8)
        tile[j][tx] = Vb[(long)(t0 + j) * ATT_D + d0 + tx];
    __syncthreads();
    __nv_bfloat16* oh = VTh + (long)b * ATT_D * ATT_N;
    __nv_bfloat16* ol = VTl + (long)b * ATT_D * ATT_N;
    #pragma unroll
    for (int j = ty; j < 32; j += 8) {
        float v = tile[tx][j];
        __nv_bfloat16 h = __float2bfloat16(v);
        long idx = (long)(d0 + j) * ATT_N + t0 + tx;
        oh[idx] = h;
        ol[idx] = __float2bfloat16(v - __bfloat162float(h));
    }
}

// ---------------------------------------------------------------------------
// softmax rows of S (4096), emit P as bf16 hi/lo
// ---------------------------------------------------------------------------
__global__ __launch_bounds__(256)
void softmax_kernel(const float* __restrict__ S, __nv_bfloat16* __restrict__ Ph,
                    __nv_bfloat16* __restrict__ Pl, const float* __restrict__ scale_ptr)
{
    const long row = blockIdx.x;
    const float* p = S + row * ATT_N;
    const float inv_scale = 1.0f / scale_ptr[0];
    const int t = threadIdx.x;

    float x[16];
    float mx = -1e30f;
    #pragma unroll
    for (int i = 0; i < 16; i++) {
        x[i] = p[t + i * 256] * inv_scale;
        mx = fmaxf(mx, x[i]);
    }
    __shared__ float red[256];
    red[t] = mx;
    __syncthreads();
    #pragma unroll
    for (int s = 128; s > 0; s >>= 1) {
        if (t < s) red[t] = fmaxf(red[t], red[t + s]);
        __syncthreads();
    }
    mx = red[0];
    __syncthreads();
    float sum = 0.0f;
    #pragma unroll
    for (int i = 0; i < 16; i++) {
        x[i] = __expf(x[i] - mx);
        sum += x[i];
    }
    red[t] = sum;
    __syncthreads();
    #pragma unroll
    for (int s = 128; s > 0; s >>= 1) {
        if (t < s) red[t] += red[t + s];
        __syncthreads();
    }
    const float rinv = 1.0f / red[0];
    __nv_bfloat16* ph = Ph + row * ATT_N;
    __nv_bfloat16* pl = Pl + row * ATT_N;
    #pragma unroll
    for (int i = 0; i < 16; i++) {
        float v = x[i] * rinv;
        __nv_bfloat16 h = __float2bfloat16(v);
        ph[t + i * 256] = h;
        pl[t + i * 256] = __float2bfloat16(v - __bfloat162float(h));
    }
}

// ---------------------------------------------------------------------------
extern "C" void kernel_launch(void* const* d_in, const int* in_sizes, int n_in,
                              void* d_out, int out_size)
{
    const float* x     = (const float*)d_in[0];
    const float* Wq    = (const float*)d_in[1];
    const float* bq    = (const float*)d_in[2];
    const float* Wk    = (const float*)d_in[3];
    const float* bk    = (const float*)d_in[4];
    const float* Wv    = (const float*)d_in[5];
    const float* bv    = (const float*)d_in[6];
    const float* scale = (const float*)d_in[7];
    float* out = (float*)d_out;

    float *Q, *Kp, *V, *S;
    __nv_bfloat16 *Qh, *Ql, *Kh, *Kl, *VTh, *VTl, *Ph, *Pl;
    cudaGetSymbolAddress((void**)&Q,  g_Q);
    cudaGetSymbolAddress((void**)&Kp, g_K);
    cudaGetSymbolAddress((void**)&V,  g_V);
    cudaGetSymbolAddress((void**)&S,  g_S);
    cudaGetSymbolAddress((void**)&Qh, g_Qh);
    cudaGetSymbolAddress((void**)&Ql, g_Ql);
    cudaGetSymbolAddress((void**)&Kh, g_Kh);
    cudaGetSymbolAddress((void**)&Kl, g_Kl);
    cudaGetSymbolAddress((void**)&VTh, g_VTh);
    cudaGetSymbolAddress((void**)&VTl, g_VTl);
    cudaGetSymbolAddress((void**)&Ph, g_Ph);
    cudaGetSymbolAddress((void**)&Pl, g_Pl);

    // 1) QKV projections (fp32 SIMT, fused over z)
    {
        dim3 grid(ATT_D / BN, ATT_M / BM, 3);
        sgemm_qkv<<<grid, 256>>>(x, Wq, bq, Wk, bk, Wv, bv, Q, Kp, V,
                                 ATT_D, ATT_D);
    }

    // 2) bf16 hi/lo splits of Q, K; transpose+split V
    {
        int n4 = ATT_M * ATT_D / 4;
        split_kernel<<<(n4 + 255) / 256, 256>>>((const float4*)Q,  Qh, Ql, n4);
        split_kernel<<<(n4 + 255) / 256, 256>>>((const float4*)Kp, Kh, Kl, n4);
        vtrans_kernel<<<dim3(ATT_D / 32, ATT_N / 32, ATT_B), 256>>>(V, VTh, VTl);
    }

    // 3) S = Q @ K^T  (mma.sync bf16 3-split)
    {
        dim3 grid(ATT_N / 128, ATT_N / 128, ATT_B);
        mma_gemm<<<grid, 256>>>(Qh, Ql, Kh, Kl, S, ATT_D, ATT_N,
                                (long)ATT_N * ATT_D, (long)ATT_N * ATT_D,
                                (long)ATT_N * ATT_N);
    }

    // 4) P = softmax(S/scale) -> bf16 hi/lo
    softmax_kernel<<<ATT_B * ATT_N, 256>>>(S, Ph, Pl, scale);

    // 5) out = P @ VT^T  (mma.sync bf16 3-split)
    {
        dim3 grid(ATT_D / 128, ATT_N / 128, ATT_B);
        mma_gemm<<<grid, 256>>>(Ph, Pl, VTh, VTl, out, ATT_N, ATT_D,
                                (long)ATT_N * ATT_N, (long)ATT_D * ATT_N,
                                (long)ATT_N * ATT_D);
    }
}

// round 9
// speedup vs baseline: 2.3668x; 1.4073x over previous
#include <cuda_runtime.h>
#include <cuda_fp16.h>
#include <cstdint>

#define ATT_B 4
#define ATT_N 4096
#define ATT_D 256
#define ATT_M (ATT_B * ATT_N)   // 16384

// ---------------- scratch (no allocations allowed) ----------------
__device__ float g_Q[ATT_M * ATT_D];
__device__ float g_K[ATT_M * ATT_D];
__device__ float g_V[ATT_M * ATT_D];
__device__ float g_S[(size_t)ATT_B * ATT_N * ATT_N];            // scores fp32
__device__ __half g_Qh[ATT_M * ATT_D], g_Ql[ATT_M * ATT_D];
__device__ __half g_Kh[ATT_M * ATT_D], g_Kl[ATT_M * ATT_D];
__device__ __half g_VTh[ATT_M * ATT_D];                          // [B][D][N]
__device__ __half g_Ph[(size_t)ATT_B * ATT_N * ATT_N];

// ---------------- helpers ----------------
__device__ __forceinline__ uint32_t smem_u32(const void* p) {
    uint32_t a;
    asm("{ .reg .u64 t; cvta.to.shared.u64 t, %1; cvt.u32.u64 %0, t; }"
        : "=r"(a) : "l"(p));
    return a;
}
__device__ __forceinline__ void ldsm4(uint32_t* r, uint32_t addr) {
    asm volatile("ldmatrix.sync.aligned.m8n8.x4.shared.b16 {%0,%1,%2,%3}, [%4];"
                 : "=r"(r[0]), "=r"(r[1]), "=r"(r[2]), "=r"(r[3]) : "r"(addr));
}
__device__ __forceinline__ void mma16816(float* c, const uint32_t* a,
                                         uint32_t b0, uint32_t b1) {
    asm volatile(
        "mma.sync.aligned.m16n8k16.row.col.f32.f16.f16.f32 "
        "{%0,%1,%2,%3}, {%4,%5,%6,%7}, {%8,%9}, {%0,%1,%2,%3};"
        : "+f"(c[0]), "+f"(c[1]), "+f"(c[2]), "+f"(c[3])
        : "r"(a[0]), "r"(a[1]), "r"(a[2]), "r"(a[3]), "r"(b0), "r"(b1));
}
__device__ __forceinline__ void cp_async16(uint32_t saddr, const void* gaddr) {
    asm volatile("cp.async.ca.shared.global [%0], [%1], 16;"
                 :: "r"(saddr), "l"(gaddr) : "memory");
}
__device__ __forceinline__ void cp_commit() {
    asm volatile("cp.async.commit_group;" ::: "memory");
}
template <int N>
__device__ __forceinline__ void cp_wait() {
    asm volatile("cp.async.wait_group %0;" :: "n"(N) : "memory");
}

// ---------------------------------------------------------------------------
// Warp-MMA GEMM (HMMA via mma.sync): C[M,N] = NPHASE-term fp16 split of
// A[M,K] @ B[N,K]^T, fp32 accumulate.
// NPHASE=3: Ah*Bh + Ah*Bl + Al*Bh.  NPHASE=1: Ah*Bh only.
// BM=BN=128, BK=32, 256 threads (8 warps, 4x2), warp tile 32x64.
// Both tiles stored [row][k] in smem, pitch 40 halves (80B, conflict-free LDSM).
// ---------------------------------------------------------------------------
#define MM_PITCH 40
#define MM_TILE  (128 * MM_PITCH)   // half elements per tile buffer

template <int NPHASE>
__global__ void __launch_bounds__(256)
mma_gemm(const __half* __restrict__ Ah, const __half* __restrict__ Al,
         const __half* __restrict__ Bh, const __half* __restrict__ Bl,
         float* __restrict__ C, int K, int ldC,
         long sA, long sB, long sC)
{
    __shared__ __align__(128) __half sAt[2][MM_TILE];
    __shared__ __align__(128) __half sBt[2][MM_TILE];

    const int tid  = threadIdx.x;
    const int wid  = tid >> 5;
    const int lane = tid & 31;
    const int bz = blockIdx.z;
    const int m0 = blockIdx.y * 128;
    const int n0 = blockIdx.x * 128;
    const int wm = (wid & 3) * 32;   // warp m offset in tile
    const int wn = (wid >> 2) * 64;  // warp n offset in tile

    const __half* Ah_b = Ah + (long)bz * sA + (long)m0 * K;
    const __half* Al_b = (NPHASE == 3) ? (Al + (long)bz * sA + (long)m0 * K) : Ah_b;
    const __half* Bh_b = Bh + (long)bz * sB + (long)n0 * K;
    const __half* Bl_b = (NPHASE == 3) ? (Bl + (long)bz * sB + (long)n0 * K) : Bh_b;

    const int kch = K >> 5;           // 32-wide chunks per phase
    const int nch = NPHASE * kch;     // phases: (Ah,Bh)[,(Ah,Bl),(Al,Bh)]

    // loader mapping: 512 x 16B per tile, 2 per thread per tile
    const int lrow = tid >> 2;          // 0..63
    const int lq   = tid & 3;           // 16B column within 64B row

    auto issue_chunk = [&](int c) {
        int phase, kk;
        if (NPHASE == 1) { phase = 0; kk = c << 5; }
        else             { phase = c / kch; kk = (c - phase * kch) << 5; }
        const __half* pa = (phase == 2) ? Al_b : Ah_b;
        const __half* pb = (phase == 1) ? Bl_b : Bh_b;
        const int buf = c & 1;
        #pragma unroll
        for (int i = 0; i < 2; ++i) {
            const int row = lrow + i * 64;
            const long go = (long)row * K + kk + lq * 8;
            const uint32_t so = row * MM_PITCH + lq * 8;
            cp_async16(smem_u32(&sAt[buf][so]), pa + go);
            cp_async16(smem_u32(&sBt[buf][so]), pb + go);
        }
        cp_commit();
    };

    float acc[2][8][4];
    #pragma unroll
    for (int mi = 0; mi < 2; ++mi)
        #pragma unroll
        for (int ni = 0; ni < 8; ++ni)
            #pragma unroll
            for (int j = 0; j < 4; ++j) acc[mi][ni][j] = 0.0f;

    issue_chunk(0);

    for (int c = 0; c < nch; ++c) {
        if (c + 1 < nch) { issue_chunk(c + 1); cp_wait<1>(); }
        else             { cp_wait<0>(); }
        __syncthreads();

        const int buf = c & 1;
        const uint32_t abase = smem_u32(&sAt[buf][0]);
        const uint32_t bbase = smem_u32(&sBt[buf][0]);
        const int lr = lane & 15;          // ldmatrix row within 16
        const int lc = (lane >> 4) * 16;   // 16B column selector (bytes)

        #pragma unroll
        for (int s = 0; s < 2; ++s) {      // two k16 steps in BK=32
            const uint32_t kb = s * 32 + lc;   // byte offset in row
            uint32_t afr[2][4];
            #pragma unroll
            for (int mi = 0; mi < 2; ++mi)
                ldsm4(afr[mi], abase + (wm + mi * 16 + lr) * (MM_PITCH * 2) + kb);
            uint32_t bfr[4][4];
            #pragma unroll
            for (int nj = 0; nj < 4; ++nj)
                ldsm4(bfr[nj], bbase + (wn + nj * 16 + lr) * (MM_PITCH * 2) + kb);
            #pragma unroll
            for (int mi = 0; mi < 2; ++mi)
                #pragma unroll
                for (int nj = 0; nj < 4; ++nj) {
                    mma16816(acc[mi][nj * 2 + 0], afr[mi], bfr[nj][0], bfr[nj][2]);
                    mma16816(acc[mi][nj * 2 + 1], afr[mi], bfr[nj][1], bfr[nj][3]);
                }
        }
        __syncthreads();
    }

    // epilogue: thread owns rows (lane/4, +8) cols (lane%4)*2 within each m16n8
    float* Cb = C + (long)bz * sC;
    #pragma unroll
    for (int mi = 0; mi < 2; ++mi) {
        const long r0 = m0 + wm + mi * 16 + (lane >> 2);
        #pragma unroll
        for (int ni = 0; ni < 8; ++ni) {
            const int col = n0 + wn + ni * 8 + (lane & 3) * 2;
            float2 v0 = make_float2(acc[mi][ni][0], acc[mi][ni][1]);
            float2 v1 = make_float2(acc[mi][ni][2], acc[mi][ni][3]);
            *(float2*)(Cb + r0 * ldC + col)       = v0;
            *(float2*)(Cb + (r0 + 8) * ldC + col) = v1;
        }
    }
}

// ---------------------------------------------------------------------------
// SIMT SGEMM for QKV projections, fused: z selects (Wq,bq)/(Wk,bk)/(Wv,bv)
// ---------------------------------------------------------------------------
#define BM 128
#define BN 128
#define BK 16
#define PAD 4

__global__ __launch_bounds__(256)
void sgemm_qkv(const float* __restrict__ A,
               const float* __restrict__ W0, const float* __restrict__ b0,
               const float* __restrict__ W1, const float* __restrict__ b1,
               const float* __restrict__ W2, const float* __restrict__ b2,
               float* __restrict__ C0, float* __restrict__ C1, float* __restrict__ C2,
               int K, int N)
{
    const int z = blockIdx.z;
    const float* W    = (z == 0) ? W0 : (z == 1) ? W1 : W2;
    const float* bias = (z == 0) ? b0 : (z == 1) ? b1 : b2;
    float* C          = (z == 0) ? C0 : (z == 1) ? C1 : C2;

    __shared__ float As[BK][BM + PAD];
    __shared__ float Bs[BK][BN + PAD];
    const int cRow = blockIdx.y, cCol = blockIdx.x, tid = threadIdx.x;
    const int tx = tid % 16, ty = tid / 16;
    const float* Aptr = A + (long)cRow * BM * K;
    const float* Bptr = W + (long)cCol * BN * K;
    const int aRow = tid / 4, aCol = (tid % 4) * 4;
    float acc[8][8] = {};

    for (int k0 = 0; k0 < K; k0 += BK) {
        #pragma unroll
        for (int r = 0; r < 2; r++) {
            int m = aRow + r * 64;
            float4 v = *(const float4*)(Aptr + (long)m * K + k0 + aCol);
            As[aCol+0][m]=v.x; As[aCol+1][m]=v.y; As[aCol+2][m]=v.z; As[aCol+3][m]=v.w;
            float4 w = *(const float4*)(Bptr + (long)m * K + k0 + aCol);
            Bs[aCol+0][m]=w.x; Bs[aCol+1][m]=w.y; Bs[aCol+2][m]=w.z; Bs[aCol+3][m]=w.w;
        }
        __syncthreads();
        #pragma unroll
        for (int k = 0; k < BK; k++) {
            float ra[8], rb[8];
            const float4* a4 = (const float4*)&As[k][ty * 8];
            const float4* b4 = (const float4*)&Bs[k][tx * 8];
            float4 a0=a4[0],a1=a4[1],b0v=b4[0],b1v=b4[1];
            ra[0]=a0.x;ra[1]=a0.y;ra[2]=a0.z;ra[3]=a0.w;ra[4]=a1.x;ra[5]=a1.y;ra[6]=a1.z;ra[7]=a1.w;
            rb[0]=b0v.x;rb[1]=b0v.y;rb[2]=b0v.z;rb[3]=b0v.w;rb[4]=b1v.x;rb[5]=b1v.y;rb[6]=b1v.z;rb[7]=b1v.w;
            #pragma unroll
            for (int i = 0; i < 8; i++)
                #pragma unroll
                for (int j = 0; j < 8; j++)
                    acc[i][j] += ra[i] * rb[j];
        }
        __syncthreads();
    }
    #pragma unroll
    for (int i = 0; i < 8; i++) {
        long m = (long)cRow * BM + ty * 8 + i;
        #pragma unroll
        for (int j = 0; j < 8; j += 4) {
            int n = cCol * BN + tx * 8 + j;
            float4 v;
            v.x = acc[i][j+0] + bias[n+0];
            v.y = acc[i][j+1] + bias[n+1];
            v.z = acc[i][j+2] + bias[n+2];
            v.w = acc[i][j+3] + bias[n+3];
            *(float4*)(C + m * N + n) = v;
        }
    }
}

// ---------------------------------------------------------------------------
// elementwise fp32 -> fp16 hi/lo split
// ---------------------------------------------------------------------------
__global__ __launch_bounds__(256)
void split_kernel(const float4* __restrict__ in, __half* __restrict__ hi,
                  __half* __restrict__ lo, int n4)
{
    int i = blockIdx.x * 256 + threadIdx.x;
    if (i >= n4) return;
    float4 v = in[i];
    __half h0 = __float2half_rn(v.x), h1 = __float2half_rn(v.y);
    __half h2 = __float2half_rn(v.z), h3 = __float2half_rn(v.w);
    __half2 hp0; hp0.x = h0; hp0.y = h1;
    __half2 hp1; hp1.x = h2; hp1.y = h3;
    __half2 lp0;
    lp0.x = __float2half_rn(v.x - __half2float(h0));
    lp0.y = __float2half_rn(v.y - __half2float(h1));
    __half2 lp1;
    lp1.x = __float2half_rn(v.z - __half2float(h2));
    lp1.y = __float2half_rn(v.w - __half2float(h3));
    ((__half2*)hi)[i * 2 + 0] = hp0;
    ((__half2*)hi)[i * 2 + 1] = hp1;
    ((__half2*)lo)[i * 2 + 0] = lp0;
    ((__half2*)lo)[i * 2 + 1] = lp1;
}

// ---------------------------------------------------------------------------
// V [B*N, D] -> VT [B][D][N] fp16 (32x32 smem transpose)
// ---------------------------------------------------------------------------
__global__ __launch_bounds__(256)
void vtrans_kernel(const float* __restrict__ V, __half* __restrict__ VTh)
{
    __shared__ float tile[32][33];
    const int b  = blockIdx.z;
    const int d0 = blockIdx.x * 32;
    const int t0 = blockIdx.y * 32;
    const int tx = threadIdx.x & 31;
    const int ty = threadIdx.x >> 5;   // 0..7
    const float* Vb = V + (long)b * ATT_N * ATT_D;
    #pragma unroll
    for (int j = ty; j < 32; j += 8)
        tile[j][tx] = Vb[(long)(t0 + j) * ATT_D + d0 + tx];
    __syncthreads();
    __half* oh = VTh + (long)b * ATT_D * ATT_N;
    #pragma unroll
    for (int j = ty; j < 32; j += 8) {
        float v = tile[tx][j];
        oh[(long)(d0 + j) * ATT_N + t0 + tx] = __float2half_rn(v);
    }
}

// ---------------------------------------------------------------------------
// softmax rows of S (4096), emit P as fp16
// ---------------------------------------------------------------------------
__global__ __launch_bounds__(256)
void softmax_kernel(const float* __restrict__ S, __half* __restrict__ Ph,
                    const float* __restrict__ scale_ptr)
{
    const long row = blockIdx.x;
    const float* p = S + row * ATT_N;
    const float inv_scale = 1.0f / scale_ptr[0];
    const int t = threadIdx.x;

    float x[16];
    float mx = -1e30f;
    #pragma unroll
    for (int i = 0; i < 16; i++) {
        x[i] = p[t + i * 256] * inv_scale;
        mx = fmaxf(mx, x[i]);
    }
    __shared__ float red[256];
    red[t] = mx;
    __syncthreads();
    #pragma unroll
    for (int s = 128; s > 0; s >>= 1) {
        if (t < s) red[t] = fmaxf(red[t], red[t + s]);
        __syncthreads();
    }
    mx = red[0];
    __syncthreads();
    float sum = 0.0f;
    #pragma unroll
    for (int i = 0; i < 16; i++) {
        x[i] = __expf(x[i] - mx);
        sum += x[i];
    }
    red[t] = sum;
    __syncthreads();
    #pragma unroll
    for (int s = 128; s > 0; s >>= 1) {
        if (t < s) red[t] += red[t + s];
        __syncthreads();
    }
    const float rinv = 1.0f / red[0];
    __half* ph = Ph + row * ATT_N;
    #pragma unroll
    for (int i = 0; i < 16; i++)
        ph[t + i * 256] = __float2half_rn(x[i] * rinv);
}

// ---------------------------------------------------------------------------
extern "C" void kernel_launch(void* const* d_in, const int* in_sizes, int n_in,
                              void* d_out, int out_size)
{
    const float* x     = (const float*)d_in[0];
    const float* Wq    = (const float*)d_in[1];
    const float* bq    = (const float*)d_in[2];
    const float* Wk    = (const float*)d_in[3];
    const float* bk    = (const float*)d_in[4];
    const float* Wv    = (const float*)d_in[5];
    const float* bv    = (const float*)d_in[6];
    const float* scale = (const float*)d_in[7];
    float* out = (float*)d_out;

    float *Q, *Kp, *V, *S;
    __half *Qh, *Ql, *Kh, *Kl, *VTh, *Ph;
    cudaGetSymbolAddress((void**)&Q,  g_Q);
    cudaGetSymbolAddress((void**)&Kp, g_K);
    cudaGetSymbolAddress((void**)&V,  g_V);
    cudaGetSymbolAddress((void**)&S,  g_S);
    cudaGetSymbolAddress((void**)&Qh, g_Qh);
    cudaGetSymbolAddress((void**)&Ql, g_Ql);
    cudaGetSymbolAddress((void**)&Kh, g_Kh);
    cudaGetSymbolAddress((void**)&Kl, g_Kl);
    cudaGetSymbolAddress((void**)&VTh, g_VTh);
    cudaGetSymbolAddress((void**)&Ph, g_Ph);

    // 1) QKV projections (fp32 SIMT, fused over z)
    {
        dim3 grid(ATT_D / BN, ATT_M / BM, 3);
        sgemm_qkv<<<grid, 256>>>(x, Wq, bq, Wk, bk, Wv, bv, Q, Kp, V,
                                 ATT_D, ATT_D);
    }

    // 2) fp16 hi/lo splits of Q, K; transpose V -> fp16
    {
        int n4 = ATT_M * ATT_D / 4;
        split_kernel<<<(n4 + 255) / 256, 256>>>((const float4*)Q,  Qh, Ql, n4);
        split_kernel<<<(n4 + 255) / 256, 256>>>((const float4*)Kp, Kh, Kl, n4);
        vtrans_kernel<<<dim3(ATT_D / 32, ATT_N / 32, ATT_B), 256>>>(V, VTh);
    }

    // 3) S = Q @ K^T  (mma.sync fp16 3-term split: exact to ~2^-22)
    {
        dim3 grid(ATT_N / 128, ATT_N / 128, ATT_B);
        mma_gemm<3><<<grid, 256>>>(Qh, Ql, Kh, Kl, S, ATT_D, ATT_N,
                                   (long)ATT_N * ATT_D, (long)ATT_N * ATT_D,
                                   (long)ATT_N * ATT_N);
    }

    // 4) P = softmax(S/scale) -> fp16
    softmax_kernel<<<ATT_B * ATT_N, 256>>>(S, Ph, scale);

    // 5) out = P @ VT^T  (mma.sync fp16 single pass; error ~3e-4 rel)
    {
        dim3 grid(ATT_D / 128, ATT_N / 128, ATT_B);
        mma_gemm<1><<<grid, 256>>>(Ph, nullptr, VTh, nullptr, out, ATT_N, ATT_D,
                                   (long)ATT_N * ATT_N, (long)ATT_D * ATT_N,
                                   (long)ATT_N * ATT_D);
    }
}

// round 10
// speedup vs baseline: 2.8271x; 1.1945x over previous
#include <cuda_runtime.h>
#include <cuda_fp16.h>
#include <cstdint>

#define ATT_B 4
#define ATT_N 4096
#define ATT_D 256
#define ATT_M (ATT_B * ATT_N)   // 16384

// ---------------- scratch (no allocations allowed) ----------------
__device__ float g_Q[ATT_M * ATT_D];
__device__ float g_K[ATT_M * ATT_D];
__device__ float g_V[ATT_M * ATT_D];
__device__ float g_S[(size_t)ATT_B * ATT_N * ATT_N];            // scores fp32
__device__ __half g_Qh[ATT_M * ATT_D], g_Ql[ATT_M * ATT_D];
__device__ __half g_Kh[ATT_M * ATT_D];
__device__ __half g_VTh[ATT_M * ATT_D];                          // [B][D][N]
__device__ __half g_Ph[(size_t)ATT_B * ATT_N * ATT_N];

// ---------------- helpers ----------------
__device__ __forceinline__ uint32_t smem_u32(const void* p) {
    uint32_t a;
    asm("{ .reg .u64 t; cvta.to.shared.u64 t, %1; cvt.u32.u64 %0, t; }"
        : "=r"(a) : "l"(p));
    return a;
}
__device__ __forceinline__ void ldsm4(uint32_t* r, uint32_t addr) {
    asm volatile("ldmatrix.sync.aligned.m8n8.x4.shared.b16 {%0,%1,%2,%3}, [%4];"
                 : "=r"(r[0]), "=r"(r[1]), "=r"(r[2]), "=r"(r[3]) : "r"(addr));
}
__device__ __forceinline__ void mma16816(float* c, const uint32_t* a,
                                         uint32_t b0, uint32_t b1) {
    asm volatile(
        "mma.sync.aligned.m16n8k16.row.col.f32.f16.f16.f32 "
        "{%0,%1,%2,%3}, {%4,%5,%6,%7}, {%8,%9}, {%0,%1,%2,%3};"
        : "+f"(c[0]), "+f"(c[1]), "+f"(c[2]), "+f"(c[3])
        : "r"(a[0]), "r"(a[1]), "r"(a[2]), "r"(a[3]), "r"(b0), "r"(b1));
}
__device__ __forceinline__ void cp_async16(uint32_t saddr, const void* gaddr) {
    asm volatile("cp.async.ca.shared.global [%0], [%1], 16;"
                 :: "r"(saddr), "l"(gaddr) : "memory");
}
__device__ __forceinline__ void cp_commit() {
    asm volatile("cp.async.commit_group;" ::: "memory");
}
template <int N>
__device__ __forceinline__ void cp_wait() {
    asm volatile("cp.async.wait_group %0;" :: "n"(N) : "memory");
}

// ---------------------------------------------------------------------------
// Warp-MMA GEMM (HMMA via mma.sync): C[M,N] = NPHASE-term fp16 split of
// A[M,K] @ B[N,K]^T, fp32 accumulate.
//   NPHASE=1: Ah*Bh
//   NPHASE=2: Ah*Bh + Al*Bh        (= (Ah+Al)*Bh; B single precision pass)
//   NPHASE=3: Ah*Bh + Ah*Bl + Al*Bh
// BM=BN=128, BK=32, 256 threads (8 warps, 4x2), warp tile 32x64.
// Both tiles stored [row][k] in smem, pitch 40 halves (80B, conflict-free LDSM).
// ---------------------------------------------------------------------------
#define MM_PITCH 40
#define MM_TILE  (128 * MM_PITCH)   // half elements per tile buffer

template <int NPHASE>
__global__ void __launch_bounds__(256)
mma_gemm(const __half* __restrict__ Ah, const __half* __restrict__ Al,
         const __half* __restrict__ Bh, const __half* __restrict__ Bl,
         float* __restrict__ C, int K, int ldC,
         long sA, long sB, long sC)
{
    __shared__ __align__(128) __half sAt[2][MM_TILE];
    __shared__ __align__(128) __half sBt[2][MM_TILE];

    const int tid  = threadIdx.x;
    const int wid  = tid >> 5;
    const int lane = tid & 31;
    const int bz = blockIdx.z;
    const int m0 = blockIdx.y * 128;
    const int n0 = blockIdx.x * 128;
    const int wm = (wid & 3) * 32;   // warp m offset in tile
    const int wn = (wid >> 2) * 64;  // warp n offset in tile

    const __half* Ah_b = Ah + (long)bz * sA + (long)m0 * K;
    const __half* Al_b = (NPHASE >= 2) ? (Al + (long)bz * sA + (long)m0 * K) : Ah_b;
    const __half* Bh_b = Bh + (long)bz * sB + (long)n0 * K;
    const __half* Bl_b = (NPHASE == 3) ? (Bl + (long)bz * sB + (long)n0 * K) : Bh_b;

    const int kch = K >> 5;           // 32-wide chunks per phase
    const int nch = NPHASE * kch;

    // loader mapping: 512 x 16B per tile, 2 per thread per tile
    const int lrow = tid >> 2;          // 0..63
    const int lq   = tid & 3;           // 16B column within 64B row

    auto issue_chunk = [&](int c) {
        int phase, kk;
        if (NPHASE == 1) { phase = 0; kk = c << 5; }
        else             { phase = c / kch; kk = (c - phase * kch) << 5; }
        // phase -> operand selection:
        //   NPHASE=2: 0:(Ah,Bh) 1:(Al,Bh)
        //   NPHASE=3: 0:(Ah,Bh) 1:(Ah,Bl) 2:(Al,Bh)
        const __half* pa;
        const __half* pb;
        if (NPHASE == 2) { pa = (phase == 1) ? Al_b : Ah_b; pb = Bh_b; }
        else             { pa = (phase == 2) ? Al_b : Ah_b;
                           pb = (phase == 1) ? Bl_b : Bh_b; }
        const int buf = c & 1;
        #pragma unroll
        for (int i = 0; i < 2; ++i) {
            const int row = lrow + i * 64;
            const long go = (long)row * K + kk + lq * 8;
            const uint32_t so = row * MM_PITCH + lq * 8;
            cp_async16(smem_u32(&sAt[buf][so]), pa + go);
            cp_async16(smem_u32(&sBt[buf][so]), pb + go);
        }
        cp_commit();
    };

    float acc[2][8][4];
    #pragma unroll
    for (int mi = 0; mi < 2; ++mi)
        #pragma unroll
        for (int ni = 0; ni < 8; ++ni)
            #pragma unroll
            for (int j = 0; j < 4; ++j) acc[mi][ni][j] = 0.0f;

    issue_chunk(0);

    for (int c = 0; c < nch; ++c) {
        if (c + 1 < nch) { issue_chunk(c + 1); cp_wait<1>(); }
        else             { cp_wait<0>(); }
        __syncthreads();

        const int buf = c & 1;
        const uint32_t abase = smem_u32(&sAt[buf][0]);
        const uint32_t bbase = smem_u32(&sBt[buf][0]);
        const int lr = lane & 15;          // ldmatrix row within 16
        const int lc = (lane >> 4) * 16;   // 16B column selector (bytes)

        #pragma unroll
        for (int s = 0; s < 2; ++s) {      // two k16 steps in BK=32
            const uint32_t kb = s * 32 + lc;   // byte offset in row
            uint32_t afr[2][4];
            #pragma unroll
            for (int mi = 0; mi < 2; ++mi)
                ldsm4(afr[mi], abase + (wm + mi * 16 + lr) * (MM_PITCH * 2) + kb);
            uint32_t bfr[4][4];
            #pragma unroll
            for (int nj = 0; nj < 4; ++nj)
                ldsm4(bfr[nj], bbase + (wn + nj * 16 + lr) * (MM_PITCH * 2) + kb);
            #pragma unroll
            for (int mi = 0; mi < 2; ++mi)
                #pragma unroll
                for (int nj = 0; nj < 4; ++nj) {
                    mma16816(acc[mi][nj * 2 + 0], afr[mi], bfr[nj][0], bfr[nj][2]);
                    mma16816(acc[mi][nj * 2 + 1], afr[mi], bfr[nj][1], bfr[nj][3]);
                }
        }
        __syncthreads();
    }

    // epilogue: thread owns rows (lane/4, +8) cols (lane%4)*2 within each m16n8
    float* Cb = C + (long)bz * sC;
    #pragma unroll
    for (int mi = 0; mi < 2; ++mi) {
        const long r0 = m0 + wm + mi * 16 + (lane >> 2);
        #pragma unroll
        for (int ni = 0; ni < 8; ++ni) {
            const int col = n0 + wn + ni * 8 + (lane & 3) * 2;
            float2 v0 = make_float2(acc[mi][ni][0], acc[mi][ni][1]);
            float2 v1 = make_float2(acc[mi][ni][2], acc[mi][ni][3]);
            *(float2*)(Cb + r0 * ldC + col)       = v0;
            *(float2*)(Cb + (r0 + 8) * ldC + col) = v1;
        }
    }
}

// ---------------------------------------------------------------------------
// SIMT SGEMM for QKV projections, fused: z selects (Wq,bq)/(Wk,bk)/(Wv,bv)
// ---------------------------------------------------------------------------
#define BM 128
#define BN 128
#define BK 16
#define PAD 4

__global__ __launch_bounds__(256)
void sgemm_qkv(const float* __restrict__ A,
               const float* __restrict__ W0, const float* __restrict__ b0,
               const float* __restrict__ W1, const float* __restrict__ b1,
               const float* __restrict__ W2, const float* __restrict__ b2,
               float* __restrict__ C0, float* __restrict__ C1, float* __restrict__ C2,
               int K, int N)
{
    const int z = blockIdx.z;
    const float* W    = (z == 0) ? W0 : (z == 1) ? W1 : W2;
    const float* bias = (z == 0) ? b0 : (z == 1) ? b1 : b2;
    float* C          = (z == 0) ? C0 : (z == 1) ? C1 : C2;

    __shared__ float As[BK][BM + PAD];
    __shared__ float Bs[BK][BN + PAD];
    const int cRow = blockIdx.y, cCol = blockIdx.x, tid = threadIdx.x;
    const int tx = tid % 16, ty = tid / 16;
    const float* Aptr = A + (long)cRow * BM * K;
    const float* Bptr = W + (long)cCol * BN * K;
    const int aRow = tid / 4, aCol = (tid % 4) * 4;
    float acc[8][8] = {};

    for (int k0 = 0; k0 < K; k0 += BK) {
        #pragma unroll
        for (int r = 0; r < 2; r++) {
            int m = aRow + r * 64;
            float4 v = *(const float4*)(Aptr + (long)m * K + k0 + aCol);
            As[aCol+0][m]=v.x; As[aCol+1][m]=v.y; As[aCol+2][m]=v.z; As[aCol+3][m]=v.w;
            float4 w = *(const float4*)(Bptr + (long)m * K + k0 + aCol);
            Bs[aCol+0][m]=w.x; Bs[aCol+1][m]=w.y; Bs[aCol+2][m]=w.z; Bs[aCol+3][m]=w.w;
        }
        __syncthreads();
        #pragma unroll
        for (int k = 0; k < BK; k++) {
            float ra[8], rb[8];
            const float4* a4 = (const float4*)&As[k][ty * 8];
            const float4* b4 = (const float4*)&Bs[k][tx * 8];
            float4 a0=a4[0],a1=a4[1],b0v=b4[0],b1v=b4[1];
            ra[0]=a0.x;ra[1]=a0.y;ra[2]=a0.z;ra[3]=a0.w;ra[4]=a1.x;ra[5]=a1.y;ra[6]=a1.z;ra[7]=a1.w;
            rb[0]=b0v.x;rb[1]=b0v.y;rb[2]=b0v.z;rb[3]=b0v.w;rb[4]=b1v.x;rb[5]=b1v.y;rb[6]=b1v.z;rb[7]=b1v.w;
            #pragma unroll
            for (int i = 0; i < 8; i++)
                #pragma unroll
                for (int j = 0; j < 8; j++)
                    acc[i][j] += ra[i] * rb[j];
        }
        __syncthreads();
    }
    #pragma unroll
    for (int i = 0; i < 8; i++) {
        long m = (long)cRow * BM + ty * 8 + i;
        #pragma unroll
        for (int j = 0; j < 8; j += 4) {
            int n = cCol * BN + tx * 8 + j;
            float4 v;
            v.x = acc[i][j+0] + bias[n+0];
            v.y = acc[i][j+1] + bias[n+1];
            v.z = acc[i][j+2] + bias[n+2];
            v.w = acc[i][j+3] + bias[n+3];
            *(float4*)(C + m * N + n) = v;
        }
    }
}

// ---------------------------------------------------------------------------
// elementwise fp32 -> fp16 hi/lo split
// ---------------------------------------------------------------------------
__global__ __launch_bounds__(256)
void split_kernel(const float4* __restrict__ in, __half* __restrict__ hi,
                  __half* __restrict__ lo, int n4)
{
    int i = blockIdx.x * 256 + threadIdx.x;
    if (i >= n4) return;
    float4 v = in[i];
    __half h0 = __float2half_rn(v.x), h1 = __float2half_rn(v.y);
    __half h2 = __float2half_rn(v.z), h3 = __float2half_rn(v.w);
    __half2 hp0; hp0.x = h0; hp0.y = h1;
    __half2 hp1; hp1.x = h2; hp1.y = h3;
    __half2 lp0;
    lp0.x = __float2half_rn(v.x - __half2float(h0));
    lp0.y = __float2half_rn(v.y - __half2float(h1));
    __half2 lp1;
    lp1.x = __float2half_rn(v.z - __half2float(h2));
    lp1.y = __float2half_rn(v.w - __half2float(h3));
    ((__half2*)hi)[i * 2 + 0] = hp0;
    ((__half2*)hi)[i * 2 + 1] = hp1;
    ((__half2*)lo)[i * 2 + 0] = lp0;
    ((__half2*)lo)[i * 2 + 1] = lp1;
}

// ---------------------------------------------------------------------------
// elementwise fp32 -> fp16 convert (hi only)
// ---------------------------------------------------------------------------
__global__ __launch_bounds__(256)
void convert_kernel(const float4* __restrict__ in, __half* __restrict__ hi, int n4)
{
    int i = blockIdx.x * 256 + threadIdx.x;
    if (i >= n4) return;
    float4 v = in[i];
    __half2 hp0; hp0.x = __float2half_rn(v.x); hp0.y = __float2half_rn(v.y);
    __half2 hp1; hp1.x = __float2half_rn(v.z); hp1.y = __float2half_rn(v.w);
    ((__half2*)hi)[i * 2 + 0] = hp0;
    ((__half2*)hi)[i * 2 + 1] = hp1;
}

// ---------------------------------------------------------------------------
// V [B*N, D] -> VT [B][D][N] fp16 (32x32 smem transpose)
// ---------------------------------------------------------------------------
__global__ __launch_bounds__(256)
void vtrans_kernel(const float* __restrict__ V, __half* __restrict__ VTh)
{
    __shared__ float tile[32][33];
    const int b  = blockIdx.z;
    const int d0 = blockIdx.x * 32;
    const int t0 = blockIdx.y * 32;
    const int tx = threadIdx.x & 31;
    const int ty = threadIdx.x >> 5;   // 0..7
    const float* Vb = V + (long)b * ATT_N * ATT_D;
    #pragma unroll
    for (int j = ty; j < 32; j += 8)
        tile[j][tx] = Vb[(long)(t0 + j) * ATT_D + d0 + tx];
    __syncthreads();
    __half* oh = VTh + (long)b * ATT_D * ATT_N;
    #pragma unroll
    for (int j = ty; j < 32; j += 8) {
        float v = tile[tx][j];
        oh[(long)(d0 + j) * ATT_N + t0 + tx] = __float2half_rn(v);
    }
}

// ---------------------------------------------------------------------------
// softmax rows of S (4096), emit P as fp16
// ---------------------------------------------------------------------------
__global__ __launch_bounds__(256)
void softmax_kernel(const float* __restrict__ S, __half* __restrict__ Ph,
                    const float* __restrict__ scale_ptr)
{
    const long row = blockIdx.x;
    const float* p = S + row * ATT_N;
    const float inv_scale = 1.0f / scale_ptr[0];
    const int t = threadIdx.x;

    float x[16];
    float mx = -1e30f;
    #pragma unroll
    for (int i = 0; i < 16; i++) {
        x[i] = p[t + i * 256] * inv_scale;
        mx = fmaxf(mx, x[i]);
    }
    __shared__ float red[256];
    red[t] = mx;
    __syncthreads();
    #pragma unroll
    for (int s = 128; s > 0; s >>= 1) {
        if (t < s) red[t] = fmaxf(red[t], red[t + s]);
        __syncthreads();
    }
    mx = red[0];
    __syncthreads();
    float sum = 0.0f;
    #pragma unroll
    for (int i = 0; i < 16; i++) {
        x[i] = __expf(x[i] - mx);
        sum += x[i];
    }
    red[t] = sum;
    __syncthreads();
    #pragma unroll
    for (int s = 128; s > 0; s >>= 1) {
        if (t < s) red[t] += red[t + s];
        __syncthreads();
    }
    const float rinv = 1.0f / red[0];
    __half* ph = Ph + row * ATT_N;
    #pragma unroll
    for (int i = 0; i < 16; i++)
        ph[t + i * 256] = __float2half_rn(x[i] * rinv);
}

// ---------------------------------------------------------------------------
extern "C" void kernel_launch(void* const* d_in, const int* in_sizes, int n_in,
                              void* d_out, int out_size)
{
    const float* x     = (const float*)d_in[0];
    const float* Wq    = (const float*)d_in[1];
    const float* bq    = (const float*)d_in[2];
    const float* Wk    = (const float*)d_in[3];
    const float* bk    = (const float*)d_in[4];
    const float* Wv    = (const float*)d_in[5];
    const float* bv    = (const float*)d_in[6];
    const float* scale = (const float*)d_in[7];
    float* out = (float*)d_out;

    float *Q, *Kp, *V, *S;
    __half *Qh, *Ql, *Kh, *VTh, *Ph;
    cudaGetSymbolAddress((void**)&Q,  g_Q);
    cudaGetSymbolAddress((void**)&Kp, g_K);
    cudaGetSymbolAddress((void**)&V,  g_V);
    cudaGetSymbolAddress((void**)&S,  g_S);
    cudaGetSymbolAddress((void**)&Qh, g_Qh);
    cudaGetSymbolAddress((void**)&Ql, g_Ql);
    cudaGetSymbolAddress((void**)&Kh, g_Kh);
    cudaGetSymbolAddress((void**)&VTh, g_VTh);
    cudaGetSymbolAddress((void**)&Ph, g_Ph);

    // 1) QKV projections (fp32 SIMT, fused over z)
    {
        dim3 grid(ATT_D / BN, ATT_M / BM, 3);
        sgemm_qkv<<<grid, 256>>>(x, Wq, bq, Wk, bk, Wv, bv, Q, Kp, V,
                                 ATT_D, ATT_D);
    }

    // 2) fp16 hi/lo split of Q; fp16 convert of K; transpose V -> fp16
    {
        int n4 = ATT_M * ATT_D / 4;
        split_kernel<<<(n4 + 255) / 256, 256>>>((const float4*)Q, Qh, Ql, n4);
        convert_kernel<<<(n4 + 255) / 256, 256>>>((const float4*)Kp, Kh, n4);
        vtrans_kernel<<<dim3(ATT_D / 32, ATT_N / 32, ATT_B), 256>>>(V, VTh);
    }

    // 3) S = Q @ K^T  (mma.sync fp16 2-pass: (Qh+Ql) @ Kh; err ~2^-12 on K only)
    {
        dim3 grid(ATT_N / 128, ATT_N / 128, ATT_B);
        mma_gemm<2><<<grid, 256>>>(Qh, Ql, Kh, nullptr, S, ATT_D, ATT_N,
                                   (long)ATT_N * ATT_D, (long)ATT_N * ATT_D,
                                   (long)ATT_N * ATT_N);
    }

    // 4) P = softmax(S/scale) -> fp16
    softmax_kernel<<<ATT_B * ATT_N, 256>>>(S, Ph, scale);

    // 5) out = P @ VT^T  (mma.sync fp16 single pass; err ~1e-4 measured basis)
    {
        dim3 grid(ATT_D / 128, ATT_N / 128, ATT_B);
        mma_gemm<1><<<grid, 256>>>(Ph, nullptr, VTh, nullptr, out, ATT_N, ATT_D,
                                   (long)ATT_N * ATT_N, (long)ATT_D * ATT_N,
                                   (long)ATT_N * ATT_D);
    }
}

// round 11
// speedup vs baseline: 3.5728x; 1.2638x over previous
#include <cuda_runtime.h>
#include <cuda_fp16.h>
#include <cstdint>

#define ATT_B 4
#define ATT_N 4096
#define ATT_D 256
#define ATT_M (ATT_B * ATT_N)   // 16384

// ---------------- scratch (no allocations allowed) ----------------
__device__ float g_V[ATT_M * ATT_D];
__device__ float g_S[(size_t)ATT_B * ATT_N * ATT_N];            // scores fp32
__device__ __half g_Qh[ATT_M * ATT_D];
__device__ __half g_Kh[ATT_M * ATT_D];
__device__ __half g_VTh[ATT_M * ATT_D];                          // [B][D][N]
__device__ __half g_Ph[(size_t)ATT_B * ATT_N * ATT_N];

// ---------------- helpers ----------------
__device__ __forceinline__ uint32_t smem_u32(const void* p) {
    uint32_t a;
    asm("{ .reg .u64 t; cvta.to.shared.u64 t, %1; cvt.u32.u64 %0, t; }"
        : "=r"(a) : "l"(p));
    return a;
}
__device__ __forceinline__ void ldsm4(uint32_t* r, uint32_t addr) {
    asm volatile("ldmatrix.sync.aligned.m8n8.x4.shared.b16 {%0,%1,%2,%3}, [%4];"
                 : "=r"(r[0]), "=r"(r[1]), "=r"(r[2]), "=r"(r[3]) : "r"(addr));
}
__device__ __forceinline__ void mma16816(float* c, const uint32_t* a,
                                         uint32_t b0, uint32_t b1) {
    asm volatile(
        "mma.sync.aligned.m16n8k16.row.col.f32.f16.f16.f32 "
        "{%0,%1,%2,%3}, {%4,%5,%6,%7}, {%8,%9}, {%0,%1,%2,%3};"
        : "+f"(c[0]), "+f"(c[1]), "+f"(c[2]), "+f"(c[3])
        : "r"(a[0]), "r"(a[1]), "r"(a[2]), "r"(a[3]), "r"(b0), "r"(b1));
}
__device__ __forceinline__ void cp_async16(uint32_t saddr, const void* gaddr) {
    asm volatile("cp.async.ca.shared.global [%0], [%1], 16;"
                 :: "r"(saddr), "l"(gaddr) : "memory");
}
__device__ __forceinline__ void cp_commit() {
    asm volatile("cp.async.commit_group;" ::: "memory");
}
template <int N>
__device__ __forceinline__ void cp_wait() {
    asm volatile("cp.async.wait_group %0;" :: "n"(N) : "memory");
}

// ---------------------------------------------------------------------------
// Warp-MMA GEMM (HMMA via mma.sync): C[M,N] = NPHASE-term fp16 split of
// A[M,K] @ B[N,K]^T, fp32 accumulate.
//   NPHASE=1: Ah*Bh
//   NPHASE=2: Ah*Bh + Al*Bh
//   NPHASE=3: Ah*Bh + Ah*Bl + Al*Bh
// BM=BN=128, BK=32, 256 threads (8 warps, 4x2), warp tile 32x64.
// Both tiles stored [row][k] in smem, pitch 40 halves (80B, conflict-free LDSM).
// ---------------------------------------------------------------------------
#define MM_PITCH 40
#define MM_TILE  (128 * MM_PITCH)   // half elements per tile buffer

template <int NPHASE>
__global__ void __launch_bounds__(256)
mma_gemm(const __half* __restrict__ Ah, const __half* __restrict__ Al,
         const __half* __restrict__ Bh, const __half* __restrict__ Bl,
         float* __restrict__ C, int K, int ldC,
         long sA, long sB, long sC)
{
    __shared__ __align__(128) __half sAt[2][MM_TILE];
    __shared__ __align__(128) __half sBt[2][MM_TILE];

    const int tid  = threadIdx.x;
    const int wid  = tid >> 5;
    const int lane = tid & 31;
    const int bz = blockIdx.z;
    const int m0 = blockIdx.y * 128;
    const int n0 = blockIdx.x * 128;
    const int wm = (wid & 3) * 32;   // warp m offset in tile
    const int wn = (wid >> 2) * 64;  // warp n offset in tile

    const __half* Ah_b = Ah + (long)bz * sA + (long)m0 * K;
    const __half* Al_b = (NPHASE >= 2) ? (Al + (long)bz * sA + (long)m0 * K) : Ah_b;
    const __half* Bh_b = Bh + (long)bz * sB + (long)n0 * K;
    const __half* Bl_b = (NPHASE == 3) ? (Bl + (long)bz * sB + (long)n0 * K) : Bh_b;

    const int kch = K >> 5;           // 32-wide chunks per phase
    const int nch = NPHASE * kch;

    // loader mapping: 512 x 16B per tile, 2 per thread per tile
    const int lrow = tid >> 2;          // 0..63
    const int lq   = tid & 3;           // 16B column within 64B row

    auto issue_chunk = [&](int c) {
        int phase, kk;
        if (NPHASE == 1) { phase = 0; kk = c << 5; }
        else             { phase = c / kch; kk = (c - phase * kch) << 5; }
        const __half* pa;
        const __half* pb;
        if (NPHASE == 2) { pa = (phase == 1) ? Al_b : Ah_b; pb = Bh_b; }
        else             { pa = (phase == 2) ? Al_b : Ah_b;
                           pb = (phase == 1) ? Bl_b : Bh_b; }
        const int buf = c & 1;
        #pragma unroll
        for (int i = 0; i < 2; ++i) {
            const int row = lrow + i * 64;
            const long go = (long)row * K + kk + lq * 8;
            const uint32_t so = row * MM_PITCH + lq * 8;
            cp_async16(smem_u32(&sAt[buf][so]), pa + go);
            cp_async16(smem_u32(&sBt[buf][so]), pb + go);
        }
        cp_commit();
    };

    float acc[2][8][4];
    #pragma unroll
    for (int mi = 0; mi < 2; ++mi)
        #pragma unroll
        for (int ni = 0; ni < 8; ++ni)
            #pragma unroll
            for (int j = 0; j < 4; ++j) acc[mi][ni][j] = 0.0f;

    issue_chunk(0);

    for (int c = 0; c < nch; ++c) {
        if (c + 1 < nch) { issue_chunk(c + 1); cp_wait<1>(); }
        else             { cp_wait<0>(); }
        __syncthreads();

        const int buf = c & 1;
        const uint32_t abase = smem_u32(&sAt[buf][0]);
        const uint32_t bbase = smem_u32(&sBt[buf][0]);
        const int lr = lane & 15;          // ldmatrix row within 16
        const int lc = (lane >> 4) * 16;   // 16B column selector (bytes)

        #pragma unroll
        for (int s = 0; s < 2; ++s) {      // two k16 steps in BK=32
            const uint32_t kb = s * 32 + lc;   // byte offset in row
            uint32_t afr[2][4];
            #pragma unroll
            for (int mi = 0; mi < 2; ++mi)
                ldsm4(afr[mi], abase + (wm + mi * 16 + lr) * (MM_PITCH * 2) + kb);
            uint32_t bfr[4][4];
            #pragma unroll
            for (int nj = 0; nj < 4; ++nj)
                ldsm4(bfr[nj], bbase + (wn + nj * 16 + lr) * (MM_PITCH * 2) + kb);
            #pragma unroll
            for (int mi = 0; mi < 2; ++mi)
                #pragma unroll
                for (int nj = 0; nj < 4; ++nj) {
                    mma16816(acc[mi][nj * 2 + 0], afr[mi], bfr[nj][0], bfr[nj][2]);
                    mma16816(acc[mi][nj * 2 + 1], afr[mi], bfr[nj][1], bfr[nj][3]);
                }
        }
        __syncthreads();
    }

    // epilogue
    float* Cb = C + (long)bz * sC;
    #pragma unroll
    for (int mi = 0; mi < 2; ++mi) {
        const long r0 = m0 + wm + mi * 16 + (lane >> 2);
        #pragma unroll
        for (int ni = 0; ni < 8; ++ni) {
            const int col = n0 + wn + ni * 8 + (lane & 3) * 2;
            float2 v0 = make_float2(acc[mi][ni][0], acc[mi][ni][1]);
            float2 v1 = make_float2(acc[mi][ni][2], acc[mi][ni][3]);
            *(float2*)(Cb + r0 * ldC + col)       = v0;
            *(float2*)(Cb + (r0 + 8) * ldC + col) = v1;
        }
    }
}

// ---------------------------------------------------------------------------
// SIMT SGEMM for QKV projections, fused over z.
// z=0 -> Qh (fp16), z=1 -> Kh (fp16), z=2 -> V (fp32, for vtrans).
// ---------------------------------------------------------------------------
#define BM 128
#define BN 128
#define BK 16
#define PAD 4

__global__ __launch_bounds__(256)
void sgemm_qkv(const float* __restrict__ A,
               const float* __restrict__ W0, const float* __restrict__ b0,
               const float* __restrict__ W1, const float* __restrict__ b1,
               const float* __restrict__ W2, const float* __restrict__ b2,
               __half* __restrict__ Qh, __half* __restrict__ Kh,
               float* __restrict__ Vf,
               int K, int N)
{
    const int z = blockIdx.z;
    const float* W    = (z == 0) ? W0 : (z == 1) ? W1 : W2;
    const float* bias = (z == 0) ? b0 : (z == 1) ? b1 : b2;

    __shared__ float As[BK][BM + PAD];
    __shared__ float Bs[BK][BN + PAD];
    const int cRow = blockIdx.y, cCol = blockIdx.x, tid = threadIdx.x;
    const int tx = tid % 16, ty = tid / 16;
    const float* Aptr = A + (long)cRow * BM * K;
    const float* Bptr = W + (long)cCol * BN * K;
    const int aRow = tid / 4, aCol = (tid % 4) * 4;
    float acc[8][8] = {};

    for (int k0 = 0; k0 < K; k0 += BK) {
        #pragma unroll
        for (int r = 0; r < 2; r++) {
            int m = aRow + r * 64;
            float4 v = *(const float4*)(Aptr + (long)m * K + k0 + aCol);
            As[aCol+0][m]=v.x; As[aCol+1][m]=v.y; As[aCol+2][m]=v.z; As[aCol+3][m]=v.w;
            float4 w = *(const float4*)(Bptr + (long)m * K + k0 + aCol);
            Bs[aCol+0][m]=w.x; Bs[aCol+1][m]=w.y; Bs[aCol+2][m]=w.z; Bs[aCol+3][m]=w.w;
        }
        __syncthreads();
        #pragma unroll
        for (int k = 0; k < BK; k++) {
            float ra[8], rb[8];
            const float4* a4 = (const float4*)&As[k][ty * 8];
            const float4* b4 = (const float4*)&Bs[k][tx * 8];
            float4 a0=a4[0],a1=a4[1],b0v=b4[0],b1v=b4[1];
            ra[0]=a0.x;ra[1]=a0.y;ra[2]=a0.z;ra[3]=a0.w;ra[4]=a1.x;ra[5]=a1.y;ra[6]=a1.z;ra[7]=a1.w;
            rb[0]=b0v.x;rb[1]=b0v.y;rb[2]=b0v.z;rb[3]=b0v.w;rb[4]=b1v.x;rb[5]=b1v.y;rb[6]=b1v.z;rb[7]=b1v.w;
            #pragma unroll
            for (int i = 0; i < 8; i++)
                #pragma unroll
                for (int j = 0; j < 8; j++)
                    acc[i][j] += ra[i] * rb[j];
        }
        __syncthreads();
    }

    if (z < 2) {
        __half* C = (z == 0) ? Qh : Kh;
        #pragma unroll
        for (int i = 0; i < 8; i++) {
            long m = (long)cRow * BM + ty * 8 + i;
            int n = cCol * BN + tx * 8;
            __half2 h[4];
            #pragma unroll
            for (int j = 0; j < 4; j++) {
                h[j].x = __float2half_rn(acc[i][2*j]   + bias[n + 2*j]);
                h[j].y = __float2half_rn(acc[i][2*j+1] + bias[n + 2*j + 1]);
            }
            *(uint4*)(C + m * N + n) = *(uint4*)h;
        }
    } else {
        #pragma unroll
        for (int i = 0; i < 8; i++) {
            long m = (long)cRow * BM + ty * 8 + i;
            #pragma unroll
            for (int j = 0; j < 8; j += 4) {
                int n = cCol * BN + tx * 8 + j;
                float4 v;
                v.x = acc[i][j+0] + bias[n+0];
                v.y = acc[i][j+1] + bias[n+1];
                v.z = acc[i][j+2] + bias[n+2];
                v.w = acc[i][j+3] + bias[n+3];
                *(float4*)(Vf + m * N + n) = v;
            }
        }
    }
}

// ---------------------------------------------------------------------------
// V [B*N, D] -> VT [B][D][N] fp16 (32x32 smem transpose)
// ---------------------------------------------------------------------------
__global__ __launch_bounds__(256)
void vtrans_kernel(const float* __restrict__ V, __half* __restrict__ VTh)
{
    __shared__ float tile[32][33];
    const int b  = blockIdx.z;
    const int d0 = blockIdx.x * 32;
    const int t0 = blockIdx.y * 32;
    const int tx = threadIdx.x & 31;
    const int ty = threadIdx.x >> 5;   // 0..7
    const float* Vb = V + (long)b * ATT_N * ATT_D;
    #pragma unroll
    for (int j = ty; j < 32; j += 8)
        tile[j][tx] = Vb[(long)(t0 + j) * ATT_D + d0 + tx];
    __syncthreads();
    __half* oh = VTh + (long)b * ATT_D * ATT_N;
    #pragma unroll
    for (int j = ty; j < 32; j += 8) {
        float v = tile[tx][j];
        oh[(long)(d0 + j) * ATT_N + t0 + tx] = __float2half_rn(v);
    }
}

// ---------------------------------------------------------------------------
// softmax rows of S (4096), emit P as fp16.
// Warp-shuffle reductions; only 2 __syncthreads per phase.
// ---------------------------------------------------------------------------
__global__ __launch_bounds__(256)
void softmax_kernel(const float* __restrict__ S, __half* __restrict__ Ph,
                    const float* __restrict__ scale_ptr)
{
    const long row = blockIdx.x;
    const float* p = S + row * ATT_N;
    const float inv_scale = 1.0f / scale_ptr[0];
    const int t = threadIdx.x;
    const int lane = t & 31;
    const int warp = t >> 5;

    __shared__ float wmax[8];
    __shared__ float wsum[8];

    float x[16];
    float mx = -1e30f;
    #pragma unroll
    for (int i = 0; i < 16; i++) {
        x[i] = p[t + i * 256] * inv_scale;
        mx = fmaxf(mx, x[i]);
    }
    #pragma unroll
    for (int o = 16; o > 0; o >>= 1)
        mx = fmaxf(mx, __shfl_xor_sync(0xFFFFFFFFu, mx, o));
    if (lane == 0) wmax[warp] = mx;
    __syncthreads();
    float m = wmax[0];
    #pragma unroll
    for (int w = 1; w < 8; w++) m = fmaxf(m, wmax[w]);

    float sum = 0.0f;
    #pragma unroll
    for (int i = 0; i < 16; i++) {
        x[i] = __expf(x[i] - m);
        sum += x[i];
    }
    #pragma unroll
    for (int o = 16; o > 0; o >>= 1)
        sum += __shfl_xor_sync(0xFFFFFFFFu, sum, o);
    if (lane == 0) wsum[warp] = sum;
    __syncthreads();
    float tot = wsum[0];
    #pragma unroll
    for (int w = 1; w < 8; w++) tot += wsum[w];

    const float rinv = 1.0f / tot;
    __half* ph = Ph + row * ATT_N;
    #pragma unroll
    for (int i = 0; i < 16; i += 2) {
        __half2 h;
        h.x = __float2half_rn(x[i]     * rinv);
        h.y = __float2half_rn(x[i + 1] * rinv);
        // x[i] and x[i+1] are 256 apart in the row; store separately
        ph[t + i * 256]       = h.x;
        ph[t + (i + 1) * 256] = h.y;
    }
}

// ---------------------------------------------------------------------------
extern "C" void kernel_launch(void* const* d_in, const int* in_sizes, int n_in,
                              void* d_out, int out_size)
{
    const float* x     = (const float*)d_in[0];
    const float* Wq    = (const float*)d_in[1];
    const float* bq    = (const float*)d_in[2];
    const float* Wk    = (const float*)d_in[3];
    const float* bk    = (const float*)d_in[4];
    const float* Wv    = (const float*)d_in[5];
    const float* bv    = (const float*)d_in[6];
    const float* scale = (const float*)d_in[7];
    float* out = (float*)d_out;

    float *V, *S;
    __half *Qh, *Kh, *VTh, *Ph;
    cudaGetSymbolAddress((void**)&V,  g_V);
    cudaGetSymbolAddress((void**)&S,  g_S);
    cudaGetSymbolAddress((void**)&Qh, g_Qh);
    cudaGetSymbolAddress((void**)&Kh, g_Kh);
    cudaGetSymbolAddress((void**)&VTh, g_VTh);
    cudaGetSymbolAddress((void**)&Ph, g_Ph);

    // 1) QKV projections (fp32 SIMT; Q,K emitted directly as fp16)
    {
        dim3 grid(ATT_D / BN, ATT_M / BM, 3);
        sgemm_qkv<<<grid, 256>>>(x, Wq, bq, Wk, bk, Wv, bv, Qh, Kh, V,
                                 ATT_D, ATT_D);
    }

    // 2) transpose V -> fp16 [B][D][N]
    vtrans_kernel<<<dim3(ATT_D / 32, ATT_N / 32, ATT_B), 256>>>(V, VTh);

    // 3) S = Q @ K^T  (mma.sync fp16 single pass; err contribution ~1.1e-4)
    {
        dim3 grid(ATT_N / 128, ATT_N / 128, ATT_B);
        mma_gemm<1><<<grid, 256>>>(Qh, nullptr, Kh, nullptr, S, ATT_D, ATT_N,
                                   (long)ATT_N * ATT_D, (long)ATT_N * ATT_D,
                                   (long)ATT_N * ATT_N);
    }

    // 4) P = softmax(S/scale) -> fp16
    softmax_kernel<<<ATT_B * ATT_N, 256>>>(S, Ph, scale);

    // 5) out = P @ VT^T  (mma.sync fp16 single pass)
    {
        dim3 grid(ATT_D / 128, ATT_N / 128, ATT_B);
        mma_gemm<1><<<grid, 256>>>(Ph, nullptr, VTh, nullptr, out, ATT_N, ATT_D,
                                   (long)ATT_N * ATT_N, (long)ATT_D * ATT_N,
                                   (long)ATT_N * ATT_D);
    }
}